// round 14
// baseline (speedup 1.0000x reference)
#include <cuda_runtime.h>
#include <cuda_fp16.h>
#include <cstdint>

// ---------------- problem constants (fixed by the dataset) ----------------
#define IN_C   128
#define LEAF   50000
#define N0_MAX 100000
#define W_BAG  16
#define N1_C   25000
#define N2_C   5000
#define E1_MAX 500000
#define E2_MAX 100000

// ---------------- device scratch (allocation-free rule) -------------------
__device__ __half g_embh[(size_t)LEAF * IN_C];    // 12.8 MB fp16 emb table
__device__ __half g_h0h[(size_t)N0_MAX * IN_C];   // 25.6 MB fp16 h0
__device__ __half g_h1h[(size_t)N1_C * IN_C];     //  6.4 MB fp16 h1
__device__ __half g_A1[(size_t)N1_C * 256];       // 12.8 MB fp16 [mean|self] L1
__device__ __half g_A2[(size_t)N2_C * 256];       //  2.6 MB fp16 [mean|self] L2
__device__ int    g_off1[N1_C + 1];
__device__ int    g_off2[N2_C + 1];
__device__ int    g_cur1[N1_C];
__device__ int    g_cur2[N2_C];
__device__ int    g_adj1[E1_MAX];
__device__ int    g_adj2[E2_MAX];
__device__ __half g_Wh1[128 * 256];               // [t][k] combined (Wl|Wr), fp16
__device__ __half g_Wh2[128 * 256];

// ---------------- small asm helpers ----------------------------------------
__device__ __forceinline__ void mma_f16(float* d, const unsigned* a, const unsigned* b) {
    asm volatile(
        "mma.sync.aligned.m16n8k16.row.col.f32.f16.f16.f32 "
        "{%0,%1,%2,%3}, {%4,%5,%6,%7}, {%8,%9}, {%0,%1,%2,%3};"
        : "+f"(d[0]), "+f"(d[1]), "+f"(d[2]), "+f"(d[3])
        : "r"(a[0]), "r"(a[1]), "r"(a[2]), "r"(a[3]), "r"(b[0]), "r"(b[1]));
}
__device__ __forceinline__ void cp16(unsigned smem_dst, const void* gsrc, bool pred) {
    int sz = pred ? 16 : 0;
    asm volatile("cp.async.cg.shared.global [%0], [%1], 16, %2;"
                 :: "r"(smem_dst), "l"(gsrc), "r"(sz));
}
__device__ __forceinline__ void cp_commit() {
    asm volatile("cp.async.commit_group;");
}
__device__ __forceinline__ void cp_wait0() {
    asm volatile("cp.async.wait_group 0;");
}

// 4 halves -> float4 (8B load)
__device__ __forceinline__ float4 ld_half4(const __half* p) {
    uint2 r = __ldg((const uint2*)p);
    __half2 a = *reinterpret_cast<__half2*>(&r.x);
    __half2 b = *reinterpret_cast<__half2*>(&r.y);
    float2 fa = __half22float2(a), fb = __half22float2(b);
    return make_float4(fa.x, fa.y, fb.x, fb.y);
}
// float4 -> 4 halves (8B store)
__device__ __forceinline__ void st_half4(__half* p, float4 v) {
    __half2 a = __floats2half2_rn(v.x, v.y);
    __half2 b = __floats2half2_rn(v.z, v.w);
    uint2 r;
    r.x = *reinterpret_cast<unsigned*>(&a);
    r.y = *reinterpret_cast<unsigned*>(&b);
    *(uint2*)p = r;
}

// ---------------- main stream: fp16 emb conversion only --------------------
__global__ void init_emb(const float* __restrict__ emb) {
    int i  = blockIdx.x * blockDim.x + threadIdx.x;
    int st = gridDim.x * blockDim.x;
    for (int j = i; j < LEAF * IN_C / 4; j += st) {
        float4 v = __ldg((const float4*)(emb + (size_t)j * 4));
        st_half4(g_embh + (size_t)j * 4, v);
    }
}

// ---------------- side stream: fp16 weight prep (needed only post-join) ----
__global__ void conv_weights(const float* __restrict__ Wl1, const float* __restrict__ Wr1,
                             const float* __restrict__ Wl2, const float* __restrict__ Wr2) {
    int i = blockIdx.x * blockDim.x + threadIdx.x;
    if (i >= 128 * 256) return;
    int t = i >> 8;
    int k = i & 255;
    float w1 = (k < 128) ? Wl1[t * 128 + k] : Wr1[t * 128 + (k - 128)];
    float w2 = (k < 128) ? Wl2[t * 128 + k] : Wr2[t * 128 + (k - 128)];
    g_Wh1[i] = __float2half(w1);
    g_Wh2[i] = __float2half(w2);
}

// ---------------- side stream: zero CSR offsets -----------------------------
__global__ void zero_off() {
    int i = blockIdx.x * blockDim.x + threadIdx.x;
    if (i <= N1_C) g_off1[i] = 0;
    if (i <= N2_C) g_off2[i] = 0;
}

// ---------------- side stream: histogram (both layers) ----------------------
__global__ void hist_edges(const int* __restrict__ dst1, int E1,
                           const int* __restrict__ dst2, int E2) {
    int i = blockIdx.x * blockDim.x + threadIdx.x;
    if (i < E1) {
        atomicAdd(&g_off1[__ldg(dst1 + i) + 1], 1);
    } else if (i < E1 + E2) {
        atomicAdd(&g_off2[__ldg(dst2 + (i - E1)) + 1], 1);
    }
}

// ---------------- side stream: warp-shuffle prefix scan ---------------------
#define MAXC 25
__global__ __launch_bounds__(1024)
void scan_offsets() {
    int* off = blockIdx.x ? g_off2 : g_off1;
    int* cur = blockIdx.x ? g_cur2 : g_cur1;
    int  n   = blockIdx.x ? N2_C : N1_C;
    __shared__ int wsum[32];

    int t    = threadIdx.x;
    int lane = t & 31;
    int wid  = t >> 5;
    int C  = (n + 1023) >> 10;
    int lo = t * C;
    int hi = min(n, lo + C);
    int cnt = hi - lo; if (cnt < 0) cnt = 0;

    int v[MAXC];
#pragma unroll
    for (int j = 0; j < MAXC; ++j)
        if (j < cnt) v[j] = off[1 + lo + j];

    int s = 0;
#pragma unroll
    for (int j = 0; j < MAXC; ++j)
        if (j < cnt) s += v[j];
    int sOrig = s;

#pragma unroll
    for (int o = 1; o < 32; o <<= 1) {
        int u = __shfl_up_sync(0xffffffffu, s, o);
        if (lane >= o) s += u;
    }
    if (lane == 31) wsum[wid] = s;
    __syncthreads();
    if (wid == 0) {
        int w = wsum[lane];
#pragma unroll
        for (int o = 1; o < 32; o <<= 1) {
            int u = __shfl_up_sync(0xffffffffu, w, o);
            if (lane >= o) w += u;
        }
        wsum[lane] = w;
    }
    __syncthreads();

    int base = (wid ? wsum[wid - 1] : 0) + (s - sOrig);
    int run = base;
#pragma unroll
    for (int j = 0; j < MAXC; ++j) {
        if (j < cnt) {
            cur[lo + j] = run;
            run += v[j];
            off[1 + lo + j] = run;
        }
    }
}

// ---------------- side stream: fill adjacency (both layers) -----------------
__global__ void fill_edges(const int* __restrict__ src1, const int* __restrict__ dst1, int E1,
                           const int* __restrict__ src2, const int* __restrict__ dst2, int E2) {
    int i = blockIdx.x * blockDim.x + threadIdx.x;
    if (i < E1) {
        int d = __ldg(dst1 + i);
        int pos = atomicAdd(&g_cur1[d], 1);
        g_adj1[pos] = __ldg(src1 + i);
    } else if (i < E1 + E2) {
        int e = i - E1;
        int d = __ldg(dst2 + e);
        int pos = atomicAdd(&g_cur2[d], 1);
        g_adj2[pos] = __ldg(src2 + e);
    }
}

// ---------------- embedding bag sum + layernorm + relu (fp16 in/out) -------
__global__ void embed_ln_relu(const int* __restrict__ x, const float* __restrict__ g,
                              const float* __restrict__ b, int N0) {
    int warp = (blockIdx.x * blockDim.x + threadIdx.x) >> 5;
    int lane = threadIdx.x & 31;
    if (warp >= N0) return;

    int idx_l = (lane < W_BAG) ? __ldg(x + (size_t)warp * W_BAG + lane) : 0;

    float4 a0 = make_float4(0.f, 0.f, 0.f, 0.f);
    float4 a1 = make_float4(0.f, 0.f, 0.f, 0.f);
#pragma unroll
    for (int w = 0; w < W_BAG; w += 2) {
        int i0 = __shfl_sync(0xffffffffu, idx_l, w);
        int i1 = __shfl_sync(0xffffffffu, idx_l, w + 1);
        float4 e0 = ld_half4(g_embh + (size_t)i0 * IN_C + lane * 4);
        float4 e1 = ld_half4(g_embh + (size_t)i1 * IN_C + lane * 4);
        a0.x += e0.x; a0.y += e0.y; a0.z += e0.z; a0.w += e0.w;
        a1.x += e1.x; a1.y += e1.y; a1.z += e1.z; a1.w += e1.w;
    }
    float4 acc;
    acc.x = a0.x + a1.x; acc.y = a0.y + a1.y;
    acc.z = a0.z + a1.z; acc.w = a0.w + a1.w;

    float s = acc.x + acc.y + acc.z + acc.w;
#pragma unroll
    for (int o = 16; o; o >>= 1) s += __shfl_xor_sync(0xffffffffu, s, o);
    float mu = s * (1.0f / 128.0f);
    float d0 = acc.x - mu, d1 = acc.y - mu, d2 = acc.z - mu, d3 = acc.w - mu;
    float q = d0 * d0 + d1 * d1 + d2 * d2 + d3 * d3;
#pragma unroll
    for (int o = 16; o; o >>= 1) q += __shfl_xor_sync(0xffffffffu, q, o);
    float rs = rsqrtf(q * (1.0f / 128.0f) + 1e-5f);

    float4 gg = __ldg((const float4*)(g + lane * 4));
    float4 bb = __ldg((const float4*)(b + lane * 4));
    float4 o4;
    o4.x = fmaxf(fmaf(d0 * rs, gg.x, bb.x), 0.f);
    o4.y = fmaxf(fmaf(d1 * rs, gg.y, bb.y), 0.f);
    o4.z = fmaxf(fmaf(d2 * rs, gg.z, bb.z), 0.f);
    o4.w = fmaxf(fmaf(d3 * rs, gg.w, bb.w), 0.f);
    st_half4(g_h0h + (size_t)warp * IN_C + lane * 4, o4);
}

// ---------------- pull aggregation: A[r] = [mean | self] (fp16 out) --------
// one warp per target row; 8-edge unroll (MLP 8).
__global__ void pull_mean(const __half* __restrict__ h, const int* __restrict__ off,
                          const int* __restrict__ adj, __half* __restrict__ A, int n) {
    int warp = (blockIdx.x * blockDim.x + threadIdx.x) >> 5;
    int lane = threadIdx.x & 31;
    if (warp >= n) return;

    int o0 = __ldg(off + warp);
    int o1 = __ldg(off + warp + 1);

    float4 acc0 = make_float4(0.f, 0.f, 0.f, 0.f);
    float4 acc1 = make_float4(0.f, 0.f, 0.f, 0.f);
    int d = o0;
    for (; d + 8 <= o1; d += 8) {
        int s0 = __ldg(adj + d),     s1 = __ldg(adj + d + 1);
        int s2 = __ldg(adj + d + 2), s3 = __ldg(adj + d + 3);
        int s4 = __ldg(adj + d + 4), s5 = __ldg(adj + d + 5);
        int s6 = __ldg(adj + d + 6), s7 = __ldg(adj + d + 7);
        float4 e0 = ld_half4(h + (size_t)s0 * IN_C + lane * 4);
        float4 e1 = ld_half4(h + (size_t)s1 * IN_C + lane * 4);
        float4 e2 = ld_half4(h + (size_t)s2 * IN_C + lane * 4);
        float4 e3 = ld_half4(h + (size_t)s3 * IN_C + lane * 4);
        float4 e4 = ld_half4(h + (size_t)s4 * IN_C + lane * 4);
        float4 e5 = ld_half4(h + (size_t)s5 * IN_C + lane * 4);
        float4 e6 = ld_half4(h + (size_t)s6 * IN_C + lane * 4);
        float4 e7 = ld_half4(h + (size_t)s7 * IN_C + lane * 4);
        acc0.x += (e0.x + e2.x) + (e4.x + e6.x);
        acc0.y += (e0.y + e2.y) + (e4.y + e6.y);
        acc0.z += (e0.z + e2.z) + (e4.z + e6.z);
        acc0.w += (e0.w + e2.w) + (e4.w + e6.w);
        acc1.x += (e1.x + e3.x) + (e5.x + e7.x);
        acc1.y += (e1.y + e3.y) + (e5.y + e7.y);
        acc1.z += (e1.z + e3.z) + (e5.z + e7.z);
        acc1.w += (e1.w + e3.w) + (e5.w + e7.w);
    }
    for (; d < o1; ++d) {
        int s = __ldg(adj + d);
        float4 e = ld_half4(h + (size_t)s * IN_C + lane * 4);
        acc0.x += e.x; acc0.y += e.y; acc0.z += e.z; acc0.w += e.w;
    }
    float inv = (o1 > o0) ? (1.0f / (float)(o1 - o0)) : 0.0f;
    float4 m;
    m.x = (acc0.x + acc1.x) * inv;
    m.y = (acc0.y + acc1.y) * inv;
    m.z = (acc0.z + acc1.z) * inv;
    m.w = (acc0.w + acc1.w) * inv;
    st_half4(A + (size_t)warp * 256 + lane * 4, m);

    // self copy: raw fp16 bits, no re-rounding
    uint2 raw = __ldg((const uint2*)(h + (size_t)warp * IN_C + lane * 4));
    *(uint2*)(A + (size_t)warp * 256 + 128 + lane * 4) = raw;
}

// ---------------- fp16 tensor-core fused SAGE GEMM --------------------------
// out[n,128] = A[n,0:128] @ Wl^T + bias + A[n,128:256] @ Wr^T (+relu)
// A fp16 [n,256]; W fp16 [t][k]. 256 threads = 8 warps (2M x 4N);
// CTA tile (MFRAG*32) x 128; K chunks 32, cp.async double-buffered;
// mma.sync m16n8k16 f16, fp32 accumulate.
template<int MFRAG, int DO_RELU, int WRITE_F32, int WRITE_HALF>
__global__ __launch_bounds__(256)
void sage_gemm_f16(const __half* __restrict__ A, const __half* __restrict__ Wh,
                   const float* __restrict__ bias, float* __restrict__ out,
                   __half* __restrict__ outh, int n) {
    constexpr int TM = MFRAG * 32;

    __shared__ __half As[2][TM][40];    // stride 40: frag LDS conflict-free
    __shared__ __half Ws[2][128][40];   // [col][k]

    int tid  = threadIdx.x;
    int lane = tid & 31;
    int w    = tid >> 5;
    int g    = lane >> 2;
    int tig  = lane & 3;
    int wm   = w >> 2;      // 0..1  (M split)
    int wn   = w & 3;       // 0..3  (N split, 32 cols each)
    int row0 = blockIdx.x * TM;

    auto copyA = [&](int c, int buf) {
        for (int idx = tid; idx < TM * 4; idx += 256) {
            int r = idx >> 2, seg = idx & 3;    // 4x 16B segs per 32-half slice
            const __half* src = A + (size_t)(row0 + r) * 256 + c * 32 + seg * 8;
            cp16((unsigned)__cvta_generic_to_shared(&As[buf][r][seg * 8]),
                 src, (row0 + r) < n);
        }
    };
    auto copyW = [&](int c, int buf) {
#pragma unroll
        for (int i = 0; i < 2; ++i) {
            int idx = tid + i * 256;
            int col = idx >> 2, seg = idx & 3;
            const __half* src = Wh + (size_t)col * 256 + c * 32 + seg * 8;
            cp16((unsigned)__cvta_generic_to_shared(&Ws[buf][col][seg * 8]),
                 src, true);
        }
    };

    float acc[MFRAG][4][4];
#pragma unroll
    for (int mf = 0; mf < MFRAG; ++mf)
#pragma unroll
        for (int nt = 0; nt < 4; ++nt)
#pragma unroll
            for (int q = 0; q < 4; ++q) acc[mf][nt][q] = 0.f;

    copyA(0, 0); copyW(0, 0); cp_commit();

#pragma unroll
    for (int c = 0; c < 8; ++c) {
        int buf = c & 1;
        cp_wait0();
        __syncthreads();
        if (c < 7) { copyA(c + 1, buf ^ 1); copyW(c + 1, buf ^ 1); cp_commit(); }

#pragma unroll
        for (int ks = 0; ks < 2; ++ks) {
            int kk = ks * 16;
            unsigned a[MFRAG][4];
#pragma unroll
            for (int mf = 0; mf < MFRAG; ++mf) {
                int r0 = wm * MFRAG * 16 + mf * 16 + g;
                a[mf][0] = *(const unsigned*)&As[buf][r0][kk + tig * 2];
                a[mf][1] = *(const unsigned*)&As[buf][r0 + 8][kk + tig * 2];
                a[mf][2] = *(const unsigned*)&As[buf][r0][kk + tig * 2 + 8];
                a[mf][3] = *(const unsigned*)&As[buf][r0 + 8][kk + tig * 2 + 8];
            }
            unsigned b[4][2];
#pragma unroll
            for (int nt = 0; nt < 4; ++nt) {
                int col = wn * 32 + nt * 8 + g;
                b[nt][0] = *(const unsigned*)&Ws[buf][col][kk + tig * 2];
                b[nt][1] = *(const unsigned*)&Ws[buf][col][kk + tig * 2 + 8];
            }
#pragma unroll
            for (int mf = 0; mf < MFRAG; ++mf)
#pragma unroll
                for (int nt = 0; nt < 4; ++nt)
                    mma_f16(acc[mf][nt], a[mf], b[nt]);
        }
    }

    // epilogue: bias (+relu), fp32 and/or fp16 stores
#pragma unroll
    for (int mf = 0; mf < MFRAG; ++mf) {
        int rbase = row0 + wm * MFRAG * 16 + mf * 16 + g;
#pragma unroll
        for (int nt = 0; nt < 4; ++nt) {
            int cl = wn * 32 + nt * 8 + tig * 2;
            float2 bb = __ldg((const float2*)(bias + cl));
            float2 o0, o1;
            o0.x = acc[mf][nt][0] + bb.x;
            o0.y = acc[mf][nt][1] + bb.y;
            o1.x = acc[mf][nt][2] + bb.x;
            o1.y = acc[mf][nt][3] + bb.y;
            if (DO_RELU) {
                o0.x = fmaxf(o0.x, 0.f); o0.y = fmaxf(o0.y, 0.f);
                o1.x = fmaxf(o1.x, 0.f); o1.y = fmaxf(o1.y, 0.f);
            }
            if (rbase < n) {
                if (WRITE_F32)
                    *(float2*)(out + (size_t)rbase * 128 + cl) = o0;
                if (WRITE_HALF)
                    *(__half2*)(outh + (size_t)rbase * 128 + cl) =
                        __floats2half2_rn(o0.x, o0.y);
            }
            if (rbase + 8 < n) {
                if (WRITE_F32)
                    *(float2*)(out + (size_t)(rbase + 8) * 128 + cl) = o1;
                if (WRITE_HALF)
                    *(__half2*)(outh + (size_t)(rbase + 8) * 128 + cl) =
                        __floats2half2_rn(o1.x, o1.y);
            }
        }
    }
}

// ---------------- host launcher --------------------------------------------
extern "C" void kernel_launch(void* const* d_in, const int* in_sizes, int n_in,
                              void* d_out, int out_size) {
    int ix = 0, is1 = 1, id1 = 2, is2 = 3, id2 = 4;
    int iemb, ig, ib, iwl1, ibl1, iwr1, iwl2, ibl2, iwr2;
    if (n_in >= 16) {
        iemb = 7; ig = 8; ib = 9; iwl1 = 10; ibl1 = 11; iwr1 = 12;
        iwl2 = 13; ibl2 = 14; iwr2 = 15;
    } else {
        iemb = 5; ig = 6; ib = 7; iwl1 = 8; ibl1 = 9; iwr1 = 10;
        iwl2 = 11; ibl2 = 12; iwr2 = 13;
    }

    const int*   x    = (const int*)d_in[ix];
    const int*   src1 = (const int*)d_in[is1];
    const int*   dst1 = (const int*)d_in[id1];
    const int*   src2 = (const int*)d_in[is2];
    const int*   dst2 = (const int*)d_in[id2];
    const float* emb  = (const float*)d_in[iemb];
    const float* ln_g = (const float*)d_in[ig];
    const float* ln_b = (const float*)d_in[ib];
    const float* Wl1  = (const float*)d_in[iwl1];
    const float* bl1  = (const float*)d_in[ibl1];
    const float* Wr1  = (const float*)d_in[iwr1];
    const float* Wl2  = (const float*)d_in[iwl2];
    const float* bl2  = (const float*)d_in[ibl2];
    const float* Wr2  = (const float*)d_in[iwr2];

    int N0 = in_sizes[ix] / W_BAG;
    int E1 = in_sizes[is1]; if (E1 > E1_MAX) E1 = E1_MAX;
    int E2 = in_sizes[is2]; if (E2 > E2_MAX) E2 = E2_MAX;

    __half *h0h, *h1h, *A1, *A2, *wh1, *wh2;
    int *off1, *off2, *adj1, *adj2;
    cudaGetSymbolAddress((void**)&h0h,  g_h0h);
    cudaGetSymbolAddress((void**)&h1h,  g_h1h);
    cudaGetSymbolAddress((void**)&A1,   g_A1);
    cudaGetSymbolAddress((void**)&A2,   g_A2);
    cudaGetSymbolAddress((void**)&wh1,  g_Wh1);
    cudaGetSymbolAddress((void**)&wh2,  g_Wh2);
    cudaGetSymbolAddress((void**)&off1, g_off1);
    cudaGetSymbolAddress((void**)&off2, g_off2);
    cudaGetSymbolAddress((void**)&adj1, g_adj1);
    cudaGetSymbolAddress((void**)&adj2, g_adj2);

    // side stream + fork/join events
    cudaStream_t side;
    cudaStreamCreateWithFlags(&side, cudaStreamNonBlocking);
    cudaEvent_t eFork, eJoin;
    cudaEventCreateWithFlags(&eFork, cudaEventDisableTiming);
    cudaEventCreateWithFlags(&eJoin, cudaEventDisableTiming);

    // fork: CSR build + weight prep overlap init+embed on the main stream
    cudaEventRecord(eFork, 0);
    cudaStreamWaitEvent(side, eFork, 0);

    int Etot = E1 + E2;
    zero_off<<<(N1_C + 1024) / 1024, 1024, 0, side>>>();
    conv_weights<<<(128 * 256 + 255) / 256, 256, 0, side>>>(Wl1, Wr1, Wl2, Wr2);
    hist_edges<<<(Etot + 255) / 256, 256, 0, side>>>(dst1, E1, dst2, E2);
    scan_offsets<<<2, 1024, 0, side>>>();
    fill_edges<<<(Etot + 255) / 256, 256, 0, side>>>(src1, dst1, E1,
                                                     src2, dst2, E2);
    cudaEventRecord(eJoin, side);

    // main stream: fp16 emb conversion then embed
    init_emb<<<1024, 256>>>(emb);
    embed_ln_relu<<<(N0 * 32 + 255) / 256, 256>>>(x, ln_g, ln_b, N0);

    // join: pulls need both embed output and CSR (+weights for gemm)
    cudaStreamWaitEvent(0, eJoin, 0);

    // layer-1 pull -> A1 (fp16), GEMM -> h1h (fp16)
    pull_mean<<<(N1_C * 32 + 255) / 256, 256>>>(h0h, off1, adj1, A1, N1_C);
    sage_gemm_f16<2, 1, 0, 1><<<(N1_C + 63) / 64, 256>>>(A1, wh1, bl1,
                                                         nullptr, h1h, N1_C);

    // layer-2 pull -> A2 (fp16), GEMM -> d_out (fp32)
    pull_mean<<<(N2_C * 32 + 255) / 256, 256>>>(h1h, off2, adj2, A2, N2_C);
    sage_gemm_f16<1, 0, 1, 0><<<(N2_C + 31) / 32, 256>>>(A2, wh2, bl2,
                                                         (float*)d_out, nullptr, N2_C);
}

// round 15
// speedup vs baseline: 1.2316x; 1.2316x over previous
#include <cuda_runtime.h>
#include <cuda_fp16.h>
#include <cstdint>

// ---------------- problem constants (fixed by the dataset) ----------------
#define IN_C   128
#define LEAF   50000
#define N0_MAX 100000
#define W_BAG  16
#define N1_C   25000
#define N2_C   5000
#define E1_MAX 500000
#define E2_MAX 100000

#define NB1 25        // scan blocks for layer 1 (25*1024 >= 25000)
#define NB2 5         // scan blocks for layer 2 ( 5*1024 >=  5000)

// ---------------- device scratch (allocation-free rule) -------------------
__device__ __half g_embh[(size_t)LEAF * IN_C];    // 12.8 MB fp16 emb table
__device__ __half g_h0h[(size_t)N0_MAX * IN_C];   // 25.6 MB fp16 h0
__device__ __half g_h1h[(size_t)N1_C * IN_C];     //  6.4 MB fp16 h1
__device__ __half g_A1[(size_t)N1_C * 256];       // 12.8 MB fp16 [mean|self] L1
__device__ __half g_A2[(size_t)N2_C * 256];       //  2.6 MB fp16 [mean|self] L2
__device__ int    g_off1[N1_C + 1];
__device__ int    g_off2[N2_C + 1];
__device__ int    g_cur1[N1_C];
__device__ int    g_cur2[N2_C];
__device__ int    g_adj1[E1_MAX];
__device__ int    g_adj2[E2_MAX];
__device__ int    g_bsum1[NB1];
__device__ int    g_bsum2[NB2];
__device__ __half g_Wh1[128 * 256];               // [t][k] combined (Wl|Wr), fp16
__device__ __half g_Wh2[128 * 256];

// ---------------- small asm helpers ----------------------------------------
__device__ __forceinline__ void mma_f16(float* d, const unsigned* a, const unsigned* b) {
    asm volatile(
        "mma.sync.aligned.m16n8k16.row.col.f32.f16.f16.f32 "
        "{%0,%1,%2,%3}, {%4,%5,%6,%7}, {%8,%9}, {%0,%1,%2,%3};"
        : "+f"(d[0]), "+f"(d[1]), "+f"(d[2]), "+f"(d[3])
        : "r"(a[0]), "r"(a[1]), "r"(a[2]), "r"(a[3]), "r"(b[0]), "r"(b[1]));
}
__device__ __forceinline__ void cp16(unsigned smem_dst, const void* gsrc, bool pred) {
    int sz = pred ? 16 : 0;
    asm volatile("cp.async.cg.shared.global [%0], [%1], 16, %2;"
                 :: "r"(smem_dst), "l"(gsrc), "r"(sz));
}
__device__ __forceinline__ void cp_commit() {
    asm volatile("cp.async.commit_group;");
}
__device__ __forceinline__ void cp_wait0() {
    asm volatile("cp.async.wait_group 0;");
}

// 4 halves -> float4 (8B load)
__device__ __forceinline__ float4 ld_half4(const __half* p) {
    uint2 r = __ldg((const uint2*)p);
    __half2 a = *reinterpret_cast<__half2*>(&r.x);
    __half2 b = *reinterpret_cast<__half2*>(&r.y);
    float2 fa = __half22float2(a), fb = __half22float2(b);
    return make_float4(fa.x, fa.y, fb.x, fb.y);
}
// float4 -> 4 halves (8B store)
__device__ __forceinline__ void st_half4(__half* p, float4 v) {
    __half2 a = __floats2half2_rn(v.x, v.y);
    __half2 b = __floats2half2_rn(v.z, v.w);
    uint2 r;
    r.x = *reinterpret_cast<unsigned*>(&a);
    r.y = *reinterpret_cast<unsigned*>(&b);
    *(uint2*)p = r;
}

// ---------------- main-stream init: fp16 weight prep + fp16 emb ------------
__global__ void init_wemb(const float* __restrict__ Wl1, const float* __restrict__ Wr1,
                          const float* __restrict__ Wl2, const float* __restrict__ Wr2,
                          const float* __restrict__ emb) {
    int i  = blockIdx.x * blockDim.x + threadIdx.x;
    int st = gridDim.x * blockDim.x;
    for (int j = i; j < 128 * 256; j += st) {
        int t = j >> 8;
        int k = j & 255;
        float w1 = (k < 128) ? Wl1[t * 128 + k] : Wr1[t * 128 + (k - 128)];
        float w2 = (k < 128) ? Wl2[t * 128 + k] : Wr2[t * 128 + (k - 128)];
        g_Wh1[j] = __float2half(w1);
        g_Wh2[j] = __float2half(w2);
    }
    for (int j = i; j < LEAF * IN_C / 4; j += st) {
        float4 v = __ldg((const float4*)(emb + (size_t)j * 4));
        st_half4(g_embh + (size_t)j * 4, v);
    }
}

// ---------------- side stream: zero CSR offsets -----------------------------
__global__ void zero_off() {
    int i = blockIdx.x * blockDim.x + threadIdx.x;
    if (i <= N1_C) g_off1[i] = 0;
    if (i <= N2_C) g_off2[i] = 0;
}

// ---------------- side stream: histogram (both layers) ----------------------
__global__ void hist_edges(const int* __restrict__ dst1, int E1,
                           const int* __restrict__ dst2, int E2) {
    int i = blockIdx.x * blockDim.x + threadIdx.x;
    if (i < E1) {
        atomicAdd(&g_off1[__ldg(dst1 + i) + 1], 1);
    } else if (i < E1 + E2) {
        atomicAdd(&g_off2[__ldg(dst2 + (i - E1)) + 1], 1);
    }
}

// ---------------- side stream: multi-block scan, phase 1 --------------------
// 30 CTAs x 1024 threads: per-CTA inclusive scan of counts; block totals out.
__global__ __launch_bounds__(1024)
void scan_blocks() {
    int b = blockIdx.x;
    int *off, *cur, *bsum, n, lb;
    if (b < NB1) { off = g_off1; cur = g_cur1; bsum = g_bsum1; n = N1_C; lb = b; }
    else         { off = g_off2; cur = g_cur2; bsum = g_bsum2; n = N2_C; lb = b - NB1; }

    __shared__ int ws[32];
    int tid  = threadIdx.x;
    int lane = tid & 31;
    int wid  = tid >> 5;
    int i    = lb * 1024 + tid;

    int val = (i < n) ? off[1 + i] : 0;

    // warp inclusive scan
    int s = val;
#pragma unroll
    for (int o = 1; o < 32; o <<= 1) {
        int u = __shfl_up_sync(0xffffffffu, s, o);
        if (lane >= o) s += u;
    }
    if (lane == 31) ws[wid] = s;
    __syncthreads();
    if (wid == 0) {
        int w = ws[lane];
#pragma unroll
        for (int o = 1; o < 32; o <<= 1) {
            int u = __shfl_up_sync(0xffffffffu, w, o);
            if (lane >= o) w += u;
        }
        ws[lane] = w;
    }
    __syncthreads();

    int incl = s + (wid ? ws[wid - 1] : 0);
    if (i < n) {
        off[1 + i] = incl;        // block-local inclusive
        cur[i]     = incl - val;  // block-local exclusive (row start)
    }
    if (tid == 1023) bsum[lb] = incl;   // block total
}

// ---------------- side stream: multi-block scan, phase 2 --------------------
// each CTA adds the prefix of preceding block totals to its elements.
__global__ __launch_bounds__(1024)
void scan_add() {
    int b = blockIdx.x;
    int *off, *cur, *bsum, n, lb;
    if (b < NB1) { off = g_off1; cur = g_cur1; bsum = g_bsum1; n = N1_C; lb = b; }
    else         { off = g_off2; cur = g_cur2; bsum = g_bsum2; n = N2_C; lb = b - NB1; }
    if (lb == 0) return;   // prefix 0

    __shared__ int pfx;
    if (threadIdx.x == 0) {
        int p = 0;
        for (int j = 0; j < lb; ++j) p += bsum[j];
        pfx = p;
    }
    __syncthreads();

    int i = lb * 1024 + threadIdx.x;
    if (i < n) {
        off[1 + i] += pfx;
        cur[i]     += pfx;
    }
}

// ---------------- side stream: fill adjacency (both layers) -----------------
__global__ void fill_edges(const int* __restrict__ src1, const int* __restrict__ dst1, int E1,
                           const int* __restrict__ src2, const int* __restrict__ dst2, int E2) {
    int i = blockIdx.x * blockDim.x + threadIdx.x;
    if (i < E1) {
        int d = __ldg(dst1 + i);
        int pos = atomicAdd(&g_cur1[d], 1);
        g_adj1[pos] = __ldg(src1 + i);
    } else if (i < E1 + E2) {
        int e = i - E1;
        int d = __ldg(dst2 + e);
        int pos = atomicAdd(&g_cur2[d], 1);
        g_adj2[pos] = __ldg(src2 + e);
    }
}

// ---------------- embedding bag sum + layernorm + relu (fp16 in/out) -------
__global__ void embed_ln_relu(const int* __restrict__ x, const float* __restrict__ g,
                              const float* __restrict__ b, int N0) {
    int warp = (blockIdx.x * blockDim.x + threadIdx.x) >> 5;
    int lane = threadIdx.x & 31;
    if (warp >= N0) return;

    int idx_l = (lane < W_BAG) ? __ldg(x + (size_t)warp * W_BAG + lane) : 0;

    float4 a0 = make_float4(0.f, 0.f, 0.f, 0.f);
    float4 a1 = make_float4(0.f, 0.f, 0.f, 0.f);
#pragma unroll
    for (int w = 0; w < W_BAG; w += 2) {
        int i0 = __shfl_sync(0xffffffffu, idx_l, w);
        int i1 = __shfl_sync(0xffffffffu, idx_l, w + 1);
        float4 e0 = ld_half4(g_embh + (size_t)i0 * IN_C + lane * 4);
        float4 e1 = ld_half4(g_embh + (size_t)i1 * IN_C + lane * 4);
        a0.x += e0.x; a0.y += e0.y; a0.z += e0.z; a0.w += e0.w;
        a1.x += e1.x; a1.y += e1.y; a1.z += e1.z; a1.w += e1.w;
    }
    float4 acc;
    acc.x = a0.x + a1.x; acc.y = a0.y + a1.y;
    acc.z = a0.z + a1.z; acc.w = a0.w + a1.w;

    float s = acc.x + acc.y + acc.z + acc.w;
#pragma unroll
    for (int o = 16; o; o >>= 1) s += __shfl_xor_sync(0xffffffffu, s, o);
    float mu = s * (1.0f / 128.0f);
    float d0 = acc.x - mu, d1 = acc.y - mu, d2 = acc.z - mu, d3 = acc.w - mu;
    float q = d0 * d0 + d1 * d1 + d2 * d2 + d3 * d3;
#pragma unroll
    for (int o = 16; o; o >>= 1) q += __shfl_xor_sync(0xffffffffu, q, o);
    float rs = rsqrtf(q * (1.0f / 128.0f) + 1e-5f);

    float4 gg = __ldg((const float4*)(g + lane * 4));
    float4 bb = __ldg((const float4*)(b + lane * 4));
    float4 o4;
    o4.x = fmaxf(fmaf(d0 * rs, gg.x, bb.x), 0.f);
    o4.y = fmaxf(fmaf(d1 * rs, gg.y, bb.y), 0.f);
    o4.z = fmaxf(fmaf(d2 * rs, gg.z, bb.z), 0.f);
    o4.w = fmaxf(fmaf(d3 * rs, gg.w, bb.w), 0.f);
    st_half4(g_h0h + (size_t)warp * IN_C + lane * 4, o4);
}

// ---------------- pull aggregation: A[r] = [mean | self] (fp16 out) --------
__global__ void pull_mean(const __half* __restrict__ h, const int* __restrict__ off,
                          const int* __restrict__ adj, __half* __restrict__ A, int n) {
    int warp = (blockIdx.x * blockDim.x + threadIdx.x) >> 5;
    int lane = threadIdx.x & 31;
    if (warp >= n) return;

    int o0 = __ldg(off + warp);
    int o1 = __ldg(off + warp + 1);

    float4 acc0 = make_float4(0.f, 0.f, 0.f, 0.f);
    float4 acc1 = make_float4(0.f, 0.f, 0.f, 0.f);
    int d = o0;
    for (; d + 4 <= o1; d += 4) {
        int s0 = __ldg(adj + d);
        int s1 = __ldg(adj + d + 1);
        int s2 = __ldg(adj + d + 2);
        int s3 = __ldg(adj + d + 3);
        float4 e0 = ld_half4(h + (size_t)s0 * IN_C + lane * 4);
        float4 e1 = ld_half4(h + (size_t)s1 * IN_C + lane * 4);
        float4 e2 = ld_half4(h + (size_t)s2 * IN_C + lane * 4);
        float4 e3 = ld_half4(h + (size_t)s3 * IN_C + lane * 4);
        acc0.x += e0.x + e2.x; acc0.y += e0.y + e2.y;
        acc0.z += e0.z + e2.z; acc0.w += e0.w + e2.w;
        acc1.x += e1.x + e3.x; acc1.y += e1.y + e3.y;
        acc1.z += e1.z + e3.z; acc1.w += e1.w + e3.w;
    }
    for (; d < o1; ++d) {
        int s = __ldg(adj + d);
        float4 e = ld_half4(h + (size_t)s * IN_C + lane * 4);
        acc0.x += e.x; acc0.y += e.y; acc0.z += e.z; acc0.w += e.w;
    }
    float inv = (o1 > o0) ? (1.0f / (float)(o1 - o0)) : 0.0f;
    float4 m;
    m.x = (acc0.x + acc1.x) * inv;
    m.y = (acc0.y + acc1.y) * inv;
    m.z = (acc0.z + acc1.z) * inv;
    m.w = (acc0.w + acc1.w) * inv;
    st_half4(A + (size_t)warp * 256 + lane * 4, m);

    // self copy: raw fp16 bits, no re-rounding
    uint2 raw = __ldg((const uint2*)(h + (size_t)warp * IN_C + lane * 4));
    *(uint2*)(A + (size_t)warp * 256 + 128 + lane * 4) = raw;
}

// ---------------- fp16 tensor-core fused SAGE GEMM --------------------------
// out[n,128] = A[n,0:128] @ Wl^T + bias + A[n,128:256] @ Wr^T (+relu)
// A fp16 [n,256]; W fp16 [t][k]. 128 threads = 4 warps (2M x 2N);
// CTA tile (MFRAG*32) x 128; K chunks 32, cp.async double-buffered;
// mma.sync m16n8k16 f16, fp32 accumulate.
template<int MFRAG, int DO_RELU, int WRITE_F32, int WRITE_HALF>
__global__ __launch_bounds__(128)
void sage_gemm_f16(const __half* __restrict__ A, const __half* __restrict__ Wh,
                   const float* __restrict__ bias, float* __restrict__ out,
                   __half* __restrict__ outh, int n) {
    constexpr int TM = MFRAG * 32;

    __shared__ __half As[2][TM][40];    // stride 40 halves: frag LDS conflict-free
    __shared__ __half Ws[2][128][40];   // [col][k]

    int tid  = threadIdx.x;
    int lane = tid & 31;
    int w    = tid >> 5;
    int g    = lane >> 2;
    int tig  = lane & 3;
    int wm   = w >> 1;
    int wn   = w & 1;
    int row0 = blockIdx.x * TM;

    auto copyA = [&](int c, int buf) {
#pragma unroll
        for (int i = 0; i < TM / 32; ++i) {
            int idx = tid + i * 128;
            int r = idx >> 2, seg = idx & 3;
            const __half* src = A + (size_t)(row0 + r) * 256 + c * 32 + seg * 8;
            cp16((unsigned)__cvta_generic_to_shared(&As[buf][r][seg * 8]),
                 src, (row0 + r) < n);
        }
    };
    auto copyW = [&](int c, int buf) {
#pragma unroll
        for (int i = 0; i < 4; ++i) {
            int idx = tid + i * 128;
            int col = idx >> 2, seg = idx & 3;
            const __half* src = Wh + (size_t)col * 256 + c * 32 + seg * 8;
            cp16((unsigned)__cvta_generic_to_shared(&Ws[buf][col][seg * 8]),
                 src, true);
        }
    };

    float acc[MFRAG][8][4];
#pragma unroll
    for (int mf = 0; mf < MFRAG; ++mf)
#pragma unroll
        for (int nt = 0; nt < 8; ++nt)
#pragma unroll
            for (int q = 0; q < 4; ++q) acc[mf][nt][q] = 0.f;

    copyA(0, 0); copyW(0, 0); cp_commit();

#pragma unroll
    for (int c = 0; c < 8; ++c) {
        int buf = c & 1;
        cp_wait0();
        __syncthreads();
        if (c < 7) { copyA(c + 1, buf ^ 1); copyW(c + 1, buf ^ 1); cp_commit(); }

#pragma unroll
        for (int ks = 0; ks < 2; ++ks) {
            int kk = ks * 16;
            unsigned a[MFRAG][4];
#pragma unroll
            for (int mf = 0; mf < MFRAG; ++mf) {
                int r0 = wm * MFRAG * 16 + mf * 16 + g;
                a[mf][0] = *(const unsigned*)&As[buf][r0][kk + tig * 2];
                a[mf][1] = *(const unsigned*)&As[buf][r0 + 8][kk + tig * 2];
                a[mf][2] = *(const unsigned*)&As[buf][r0][kk + tig * 2 + 8];
                a[mf][3] = *(const unsigned*)&As[buf][r0 + 8][kk + tig * 2 + 8];
            }
            unsigned b[8][2];
#pragma unroll
            for (int nt = 0; nt < 8; ++nt) {
                int col = wn * 64 + nt * 8 + g;
                b[nt][0] = *(const unsigned*)&Ws[buf][col][kk + tig * 2];
                b[nt][1] = *(const unsigned*)&Ws[buf][col][kk + tig * 2 + 8];
            }
#pragma unroll
            for (int mf = 0; mf < MFRAG; ++mf)
#pragma unroll
                for (int nt = 0; nt < 8; ++nt)
                    mma_f16(acc[mf][nt], a[mf], b[nt]);
        }
    }

    // epilogue: bias (+relu), fp32 and/or fp16 stores
#pragma unroll
    for (int mf = 0; mf < MFRAG; ++mf) {
        int rbase = row0 + wm * MFRAG * 16 + mf * 16 + g;
#pragma unroll
        for (int nt = 0; nt < 8; ++nt) {
            int cl = wn * 64 + nt * 8 + tig * 2;
            float2 bb = __ldg((const float2*)(bias + cl));
            float2 o0, o1;
            o0.x = acc[mf][nt][0] + bb.x;
            o0.y = acc[mf][nt][1] + bb.y;
            o1.x = acc[mf][nt][2] + bb.x;
            o1.y = acc[mf][nt][3] + bb.y;
            if (DO_RELU) {
                o0.x = fmaxf(o0.x, 0.f); o0.y = fmaxf(o0.y, 0.f);
                o1.x = fmaxf(o1.x, 0.f); o1.y = fmaxf(o1.y, 0.f);
            }
            if (rbase < n) {
                if (WRITE_F32)
                    *(float2*)(out + (size_t)rbase * 128 + cl) = o0;
                if (WRITE_HALF)
                    *(__half2*)(outh + (size_t)rbase * 128 + cl) =
                        __floats2half2_rn(o0.x, o0.y);
            }
            if (rbase + 8 < n) {
                if (WRITE_F32)
                    *(float2*)(out + (size_t)(rbase + 8) * 128 + cl) = o1;
                if (WRITE_HALF)
                    *(__half2*)(outh + (size_t)(rbase + 8) * 128 + cl) =
                        __floats2half2_rn(o1.x, o1.y);
            }
        }
    }
}

// ---------------- host launcher --------------------------------------------
extern "C" void kernel_launch(void* const* d_in, const int* in_sizes, int n_in,
                              void* d_out, int out_size) {
    int ix = 0, is1 = 1, id1 = 2, is2 = 3, id2 = 4;
    int iemb, ig, ib, iwl1, ibl1, iwr1, iwl2, ibl2, iwr2;
    if (n_in >= 16) {
        iemb = 7; ig = 8; ib = 9; iwl1 = 10; ibl1 = 11; iwr1 = 12;
        iwl2 = 13; ibl2 = 14; iwr2 = 15;
    } else {
        iemb = 5; ig = 6; ib = 7; iwl1 = 8; ibl1 = 9; iwr1 = 10;
        iwl2 = 11; ibl2 = 12; iwr2 = 13;
    }

    const int*   x    = (const int*)d_in[ix];
    const int*   src1 = (const int*)d_in[is1];
    const int*   dst1 = (const int*)d_in[id1];
    const int*   src2 = (const int*)d_in[is2];
    const int*   dst2 = (const int*)d_in[id2];
    const float* emb  = (const float*)d_in[iemb];
    const float* ln_g = (const float*)d_in[ig];
    const float* ln_b = (const float*)d_in[ib];
    const float* Wl1  = (const float*)d_in[iwl1];
    const float* bl1  = (const float*)d_in[ibl1];
    const float* Wr1  = (const float*)d_in[iwr1];
    const float* Wl2  = (const float*)d_in[iwl2];
    const float* bl2  = (const float*)d_in[ibl2];
    const float* Wr2  = (const float*)d_in[iwr2];

    int N0 = in_sizes[ix] / W_BAG;
    int E1 = in_sizes[is1]; if (E1 > E1_MAX) E1 = E1_MAX;
    int E2 = in_sizes[is2]; if (E2 > E2_MAX) E2 = E2_MAX;

    __half *h0h, *h1h, *A1, *A2, *wh1, *wh2;
    int *off1, *off2, *adj1, *adj2;
    cudaGetSymbolAddress((void**)&h0h,  g_h0h);
    cudaGetSymbolAddress((void**)&h1h,  g_h1h);
    cudaGetSymbolAddress((void**)&A1,   g_A1);
    cudaGetSymbolAddress((void**)&A2,   g_A2);
    cudaGetSymbolAddress((void**)&wh1,  g_Wh1);
    cudaGetSymbolAddress((void**)&wh2,  g_Wh2);
    cudaGetSymbolAddress((void**)&off1, g_off1);
    cudaGetSymbolAddress((void**)&off2, g_off2);
    cudaGetSymbolAddress((void**)&adj1, g_adj1);
    cudaGetSymbolAddress((void**)&adj2, g_adj2);

    // side stream + fork/join events
    cudaStream_t side;
    cudaStreamCreateWithFlags(&side, cudaStreamNonBlocking);
    cudaEvent_t eFork, eJoin;
    cudaEventCreateWithFlags(&eFork, cudaEventDisableTiming);
    cudaEventCreateWithFlags(&eJoin, cudaEventDisableTiming);

    // fork: CSR build overlaps init+embed
    cudaEventRecord(eFork, 0);
    cudaStreamWaitEvent(side, eFork, 0);

    int Etot = E1 + E2;
    zero_off<<<(N1_C + 1024) / 1024, 1024, 0, side>>>();
    hist_edges<<<(Etot + 255) / 256, 256, 0, side>>>(dst1, E1, dst2, E2);
    scan_blocks<<<NB1 + NB2, 1024, 0, side>>>();
    scan_add<<<NB1 + NB2, 1024, 0, side>>>();
    fill_edges<<<(Etot + 255) / 256, 256, 0, side>>>(src1, dst1, E1,
                                                     src2, dst2, E2);
    cudaEventRecord(eJoin, side);

    // main stream: init (fp16 weights + fp16 emb) then embed
    init_wemb<<<1024, 256>>>(Wl1, Wr1, Wl2, Wr2, emb);
    embed_ln_relu<<<(N0 * 32 + 255) / 256, 256>>>(x, ln_g, ln_b, N0);

    // join: pulls need both embed output and CSR
    cudaStreamWaitEvent(0, eJoin, 0);

    // layer-1 pull -> A1 (fp16), GEMM -> h1h (fp16)
    pull_mean<<<(N1_C * 32 + 255) / 256, 256>>>(h0h, off1, adj1, A1, N1_C);
    sage_gemm_f16<2, 1, 0, 1><<<(N1_C + 63) / 64, 128>>>(A1, wh1, bl1,
                                                         nullptr, h1h, N1_C);

    // layer-2 pull -> A2 (fp16), GEMM -> d_out (fp32)
    pull_mean<<<(N2_C * 32 + 255) / 256, 256>>>(h1h, off2, adj2, A2, N2_C);
    sage_gemm_f16<1, 0, 1, 0><<<(N2_C + 31) / 32, 128>>>(A2, wh2, bl2,
                                                         (float*)d_out, nullptr, N2_C);
}

// round 16
// speedup vs baseline: 1.2697x; 1.0310x over previous
#include <cuda_runtime.h>
#include <cuda_fp16.h>
#include <cstdint>

// ---------------- problem constants (fixed by the dataset) ----------------
#define IN_C   128
#define LEAF   50000
#define N0_MAX 100000
#define W_BAG  16
#define N1_C   25000
#define N2_C   5000
#define E1_MAX 500000
#define E2_MAX 100000

#define NB1 25        // scan blocks for layer 1 (25*1024 >= 25000)
#define NB2 5         // scan blocks for layer 2 ( 5*1024 >=  5000)

// ---------------- device scratch (allocation-free rule) -------------------
__device__ __half g_embh[(size_t)LEAF * IN_C];    // 12.8 MB fp16 emb table
__device__ __half g_h0h[(size_t)N0_MAX * IN_C];   // 25.6 MB fp16 h0
__device__ __half g_h1h[(size_t)N1_C * IN_C];     //  6.4 MB fp16 h1
__device__ __half g_A1[(size_t)N1_C * 256];       // 12.8 MB fp16 [mean|self] L1
__device__ __half g_A2[(size_t)N2_C * 256];       //  2.6 MB fp16 [mean|self] L2
__device__ int    g_off1[N1_C + 1];
__device__ int    g_off2[N2_C + 1];
__device__ int    g_cur1[N1_C];
__device__ int    g_cur2[N2_C];
__device__ int    g_adj1[E1_MAX];
__device__ int    g_adj2[E2_MAX];
__device__ int    g_bsum1[NB1];
__device__ int    g_bsum2[NB2];
__device__ __half g_Wh1[128 * 256];               // [t][k] combined (Wl|Wr), fp16
__device__ __half g_Wh2[128 * 256];

// ---------------- small asm helpers ----------------------------------------
__device__ __forceinline__ void mma_f16(float* d, const unsigned* a, const unsigned* b) {
    asm volatile(
        "mma.sync.aligned.m16n8k16.row.col.f32.f16.f16.f32 "
        "{%0,%1,%2,%3}, {%4,%5,%6,%7}, {%8,%9}, {%0,%1,%2,%3};"
        : "+f"(d[0]), "+f"(d[1]), "+f"(d[2]), "+f"(d[3])
        : "r"(a[0]), "r"(a[1]), "r"(a[2]), "r"(a[3]), "r"(b[0]), "r"(b[1]));
}
__device__ __forceinline__ void cp16(unsigned smem_dst, const void* gsrc, bool pred) {
    int sz = pred ? 16 : 0;
    asm volatile("cp.async.cg.shared.global [%0], [%1], 16, %2;"
                 :: "r"(smem_dst), "l"(gsrc), "r"(sz));
}
__device__ __forceinline__ void cp_commit() {
    asm volatile("cp.async.commit_group;");
}
__device__ __forceinline__ void cp_wait0() {
    asm volatile("cp.async.wait_group 0;");
}

// 4 halves -> float4 (8B load)
__device__ __forceinline__ float4 ld_half4(const __half* p) {
    uint2 r = __ldg((const uint2*)p);
    __half2 a = *reinterpret_cast<__half2*>(&r.x);
    __half2 b = *reinterpret_cast<__half2*>(&r.y);
    float2 fa = __half22float2(a), fb = __half22float2(b);
    return make_float4(fa.x, fa.y, fb.x, fb.y);
}
// float4 -> 4 halves (8B store)
__device__ __forceinline__ void st_half4(__half* p, float4 v) {
    __half2 a = __floats2half2_rn(v.x, v.y);
    __half2 b = __floats2half2_rn(v.z, v.w);
    uint2 r;
    r.x = *reinterpret_cast<unsigned*>(&a);
    r.y = *reinterpret_cast<unsigned*>(&b);
    *(uint2*)p = r;
}

// ---------------- main-stream init: fp16 weight prep + fp16 emb ------------
__global__ void init_wemb(const float* __restrict__ Wl1, const float* __restrict__ Wr1,
                          const float* __restrict__ Wl2, const float* __restrict__ Wr2,
                          const float* __restrict__ emb) {
    int i  = blockIdx.x * blockDim.x + threadIdx.x;
    int st = gridDim.x * blockDim.x;
    for (int j = i; j < 128 * 256; j += st) {
        int t = j >> 8;
        int k = j & 255;
        float w1 = (k < 128) ? Wl1[t * 128 + k] : Wr1[t * 128 + (k - 128)];
        float w2 = (k < 128) ? Wl2[t * 128 + k] : Wr2[t * 128 + (k - 128)];
        g_Wh1[j] = __float2half(w1);
        g_Wh2[j] = __float2half(w2);
    }
    for (int j = i; j < LEAF * IN_C / 4; j += st) {
        float4 v = __ldg((const float4*)(emb + (size_t)j * 4));
        st_half4(g_embh + (size_t)j * 4, v);
    }
}

// ---------------- side stream: zero CSR offsets -----------------------------
__global__ void zero_off() {
    int i = blockIdx.x * blockDim.x + threadIdx.x;
    if (i <= N1_C) g_off1[i] = 0;
    if (i <= N2_C) g_off2[i] = 0;
}

// ---------------- side stream: histogram (both layers) ----------------------
__global__ void hist_edges(const int* __restrict__ dst1, int E1,
                           const int* __restrict__ dst2, int E2) {
    int i = blockIdx.x * blockDim.x + threadIdx.x;
    if (i < E1) {
        atomicAdd(&g_off1[__ldg(dst1 + i) + 1], 1);
    } else if (i < E1 + E2) {
        atomicAdd(&g_off2[__ldg(dst2 + (i - E1)) + 1], 1);
    }
}

// ---------------- side stream: multi-block scan, phase 1 --------------------
__global__ __launch_bounds__(1024)
void scan_blocks() {
    int b = blockIdx.x;
    int *off, *cur, *bsum, n, lb;
    if (b < NB1) { off = g_off1; cur = g_cur1; bsum = g_bsum1; n = N1_C; lb = b; }
    else         { off = g_off2; cur = g_cur2; bsum = g_bsum2; n = N2_C; lb = b - NB1; }

    __shared__ int ws[32];
    int tid  = threadIdx.x;
    int lane = tid & 31;
    int wid  = tid >> 5;
    int i    = lb * 1024 + tid;

    int val = (i < n) ? off[1 + i] : 0;

    int s = val;
#pragma unroll
    for (int o = 1; o < 32; o <<= 1) {
        int u = __shfl_up_sync(0xffffffffu, s, o);
        if (lane >= o) s += u;
    }
    if (lane == 31) ws[wid] = s;
    __syncthreads();
    if (wid == 0) {
        int w = ws[lane];
#pragma unroll
        for (int o = 1; o < 32; o <<= 1) {
            int u = __shfl_up_sync(0xffffffffu, w, o);
            if (lane >= o) w += u;
        }
        ws[lane] = w;
    }
    __syncthreads();

    int incl = s + (wid ? ws[wid - 1] : 0);
    if (i < n) {
        off[1 + i] = incl;        // block-local inclusive
        cur[i]     = incl - val;  // block-local exclusive (row start)
    }
    if (tid == 1023) bsum[lb] = incl;   // block total
}

// ---------------- side stream: multi-block scan, phase 2 --------------------
// each CTA adds the prefix of preceding block totals (warp-parallel reduce).
__global__ __launch_bounds__(1024)
void scan_add() {
    int b = blockIdx.x;
    int *off, *cur, *bsum, n, lb;
    if (b < NB1) { off = g_off1; cur = g_cur1; bsum = g_bsum1; n = N1_C; lb = b; }
    else         { off = g_off2; cur = g_cur2; bsum = g_bsum2; n = N2_C; lb = b - NB1; }
    if (lb == 0) return;   // prefix 0

    __shared__ int pfx;
    if (threadIdx.x < 32) {
        int lane = threadIdx.x;
        int v = (lane < lb) ? bsum[lane] : 0;    // independent parallel loads
#pragma unroll
        for (int o = 16; o; o >>= 1) v += __shfl_xor_sync(0xffffffffu, v, o);
        if (lane == 0) pfx = v;
    }
    __syncthreads();

    int i = lb * 1024 + threadIdx.x;
    if (i < n) {
        off[1 + i] += pfx;
        cur[i]     += pfx;
    }
}

// ---------------- side stream: fill adjacency (both layers) -----------------
__global__ void fill_edges(const int* __restrict__ src1, const int* __restrict__ dst1, int E1,
                           const int* __restrict__ src2, const int* __restrict__ dst2, int E2) {
    int i = blockIdx.x * blockDim.x + threadIdx.x;
    if (i < E1) {
        int d = __ldg(dst1 + i);
        int pos = atomicAdd(&g_cur1[d], 1);
        g_adj1[pos] = __ldg(src1 + i);
    } else if (i < E1 + E2) {
        int e = i - E1;
        int d = __ldg(dst2 + e);
        int pos = atomicAdd(&g_cur2[d], 1);
        g_adj2[pos] = __ldg(src2 + e);
    }
}

// ---------------- embedding bag sum + layernorm + relu (fp16 in/out) -------
__global__ void embed_ln_relu(const int* __restrict__ x, const float* __restrict__ g,
                              const float* __restrict__ b, int N0) {
    int warp = (blockIdx.x * blockDim.x + threadIdx.x) >> 5;
    int lane = threadIdx.x & 31;
    if (warp >= N0) return;

    int idx_l = (lane < W_BAG) ? __ldg(x + (size_t)warp * W_BAG + lane) : 0;

    float4 a0 = make_float4(0.f, 0.f, 0.f, 0.f);
    float4 a1 = make_float4(0.f, 0.f, 0.f, 0.f);
#pragma unroll
    for (int w = 0; w < W_BAG; w += 2) {
        int i0 = __shfl_sync(0xffffffffu, idx_l, w);
        int i1 = __shfl_sync(0xffffffffu, idx_l, w + 1);
        float4 e0 = ld_half4(g_embh + (size_t)i0 * IN_C + lane * 4);
        float4 e1 = ld_half4(g_embh + (size_t)i1 * IN_C + lane * 4);
        a0.x += e0.x; a0.y += e0.y; a0.z += e0.z; a0.w += e0.w;
        a1.x += e1.x; a1.y += e1.y; a1.z += e1.z; a1.w += e1.w;
    }
    float4 acc;
    acc.x = a0.x + a1.x; acc.y = a0.y + a1.y;
    acc.z = a0.z + a1.z; acc.w = a0.w + a1.w;

    float s = acc.x + acc.y + acc.z + acc.w;
#pragma unroll
    for (int o = 16; o; o >>= 1) s += __shfl_xor_sync(0xffffffffu, s, o);
    float mu = s * (1.0f / 128.0f);
    float d0 = acc.x - mu, d1 = acc.y - mu, d2 = acc.z - mu, d3 = acc.w - mu;
    float q = d0 * d0 + d1 * d1 + d2 * d2 + d3 * d3;
#pragma unroll
    for (int o = 16; o; o >>= 1) q += __shfl_xor_sync(0xffffffffu, q, o);
    float rs = rsqrtf(q * (1.0f / 128.0f) + 1e-5f);

    float4 gg = __ldg((const float4*)(g + lane * 4));
    float4 bb = __ldg((const float4*)(b + lane * 4));
    float4 o4;
    o4.x = fmaxf(fmaf(d0 * rs, gg.x, bb.x), 0.f);
    o4.y = fmaxf(fmaf(d1 * rs, gg.y, bb.y), 0.f);
    o4.z = fmaxf(fmaf(d2 * rs, gg.z, bb.z), 0.f);
    o4.w = fmaxf(fmaf(d3 * rs, gg.w, bb.w), 0.f);
    st_half4(g_h0h + (size_t)warp * IN_C + lane * 4, o4);
}

// ---------------- pull aggregation: A[r] = [mean | self] (fp16 out) --------
// one warp per target row; 8-edge unroll (MLP 8).
__global__ void pull_mean(const __half* __restrict__ h, const int* __restrict__ off,
                          const int* __restrict__ adj, __half* __restrict__ A, int n) {
    int warp = (blockIdx.x * blockDim.x + threadIdx.x) >> 5;
    int lane = threadIdx.x & 31;
    if (warp >= n) return;

    int o0 = __ldg(off + warp);
    int o1 = __ldg(off + warp + 1);

    float4 acc0 = make_float4(0.f, 0.f, 0.f, 0.f);
    float4 acc1 = make_float4(0.f, 0.f, 0.f, 0.f);
    int d = o0;
    for (; d + 8 <= o1; d += 8) {
        int s0 = __ldg(adj + d),     s1 = __ldg(adj + d + 1);
        int s2 = __ldg(adj + d + 2), s3 = __ldg(adj + d + 3);
        int s4 = __ldg(adj + d + 4), s5 = __ldg(adj + d + 5);
        int s6 = __ldg(adj + d + 6), s7 = __ldg(adj + d + 7);
        float4 e0 = ld_half4(h + (size_t)s0 * IN_C + lane * 4);
        float4 e1 = ld_half4(h + (size_t)s1 * IN_C + lane * 4);
        float4 e2 = ld_half4(h + (size_t)s2 * IN_C + lane * 4);
        float4 e3 = ld_half4(h + (size_t)s3 * IN_C + lane * 4);
        float4 e4 = ld_half4(h + (size_t)s4 * IN_C + lane * 4);
        float4 e5 = ld_half4(h + (size_t)s5 * IN_C + lane * 4);
        float4 e6 = ld_half4(h + (size_t)s6 * IN_C + lane * 4);
        float4 e7 = ld_half4(h + (size_t)s7 * IN_C + lane * 4);
        acc0.x += (e0.x + e2.x) + (e4.x + e6.x);
        acc0.y += (e0.y + e2.y) + (e4.y + e6.y);
        acc0.z += (e0.z + e2.z) + (e4.z + e6.z);
        acc0.w += (e0.w + e2.w) + (e4.w + e6.w);
        acc1.x += (e1.x + e3.x) + (e5.x + e7.x);
        acc1.y += (e1.y + e3.y) + (e5.y + e7.y);
        acc1.z += (e1.z + e3.z) + (e5.z + e7.z);
        acc1.w += (e1.w + e3.w) + (e5.w + e7.w);
    }
    for (; d < o1; ++d) {
        int s = __ldg(adj + d);
        float4 e = ld_half4(h + (size_t)s * IN_C + lane * 4);
        acc0.x += e.x; acc0.y += e.y; acc0.z += e.z; acc0.w += e.w;
    }
    float inv = (o1 > o0) ? (1.0f / (float)(o1 - o0)) : 0.0f;
    float4 m;
    m.x = (acc0.x + acc1.x) * inv;
    m.y = (acc0.y + acc1.y) * inv;
    m.z = (acc0.z + acc1.z) * inv;
    m.w = (acc0.w + acc1.w) * inv;
    st_half4(A + (size_t)warp * 256 + lane * 4, m);

    // self copy: raw fp16 bits, no re-rounding
    uint2 raw = __ldg((const uint2*)(h + (size_t)warp * IN_C + lane * 4));
    *(uint2*)(A + (size_t)warp * 256 + 128 + lane * 4) = raw;
}

// ---------------- fp16 tensor-core fused SAGE GEMM --------------------------
// out[n,128] = A[n,0:128] @ Wl^T + bias + A[n,128:256] @ Wr^T (+relu)
// A fp16 [n,256]; W fp16 [t][k]. 256 threads = 8 warps (2M x 4N);
// CTA tile (MFRAG*32) x 128; K chunks 32, cp.async double-buffered;
// mma.sync m16n8k16 f16, fp32 accumulate.
template<int MFRAG, int DO_RELU, int WRITE_F32, int WRITE_HALF>
__global__ __launch_bounds__(256)
void sage_gemm_f16(const __half* __restrict__ A, const __half* __restrict__ Wh,
                   const float* __restrict__ bias, float* __restrict__ out,
                   __half* __restrict__ outh, int n) {
    constexpr int TM = MFRAG * 32;

    __shared__ __half As[2][TM][40];    // stride 40: frag LDS conflict-free
    __shared__ __half Ws[2][128][40];   // [col][k]

    int tid  = threadIdx.x;
    int lane = tid & 31;
    int w    = tid >> 5;
    int g    = lane >> 2;
    int tig  = lane & 3;
    int wm   = w >> 2;      // 0..1  (M split)
    int wn   = w & 3;       // 0..3  (N split, 32 cols each)
    int row0 = blockIdx.x * TM;

    auto copyA = [&](int c, int buf) {
        for (int idx = tid; idx < TM * 4; idx += 256) {
            int r = idx >> 2, seg = idx & 3;    // 4x 16B segs per 32-half slice
            const __half* src = A + (size_t)(row0 + r) * 256 + c * 32 + seg * 8;
            cp16((unsigned)__cvta_generic_to_shared(&As[buf][r][seg * 8]),
                 src, (row0 + r) < n);
        }
    };
    auto copyW = [&](int c, int buf) {
#pragma unroll
        for (int i = 0; i < 2; ++i) {
            int idx = tid + i * 256;
            int col = idx >> 2, seg = idx & 3;
            const __half* src = Wh + (size_t)col * 256 + c * 32 + seg * 8;
            cp16((unsigned)__cvta_generic_to_shared(&Ws[buf][col][seg * 8]),
                 src, true);
        }
    };

    float acc[MFRAG][4][4];
#pragma unroll
    for (int mf = 0; mf < MFRAG; ++mf)
#pragma unroll
        for (int nt = 0; nt < 4; ++nt)
#pragma unroll
            for (int q = 0; q < 4; ++q) acc[mf][nt][q] = 0.f;

    copyA(0, 0); copyW(0, 0); cp_commit();

#pragma unroll
    for (int c = 0; c < 8; ++c) {
        int buf = c & 1;
        cp_wait0();
        __syncthreads();
        if (c < 7) { copyA(c + 1, buf ^ 1); copyW(c + 1, buf ^ 1); cp_commit(); }

#pragma unroll
        for (int ks = 0; ks < 2; ++ks) {
            int kk = ks * 16;
            unsigned a[MFRAG][4];
#pragma unroll
            for (int mf = 0; mf < MFRAG; ++mf) {
                int r0 = wm * MFRAG * 16 + mf * 16 + g;
                a[mf][0] = *(const unsigned*)&As[buf][r0][kk + tig * 2];
                a[mf][1] = *(const unsigned*)&As[buf][r0 + 8][kk + tig * 2];
                a[mf][2] = *(const unsigned*)&As[buf][r0][kk + tig * 2 + 8];
                a[mf][3] = *(const unsigned*)&As[buf][r0 + 8][kk + tig * 2 + 8];
            }
            unsigned b[4][2];
#pragma unroll
            for (int nt = 0; nt < 4; ++nt) {
                int col = wn * 32 + nt * 8 + g;
                b[nt][0] = *(const unsigned*)&Ws[buf][col][kk + tig * 2];
                b[nt][1] = *(const unsigned*)&Ws[buf][col][kk + tig * 2 + 8];
            }
#pragma unroll
            for (int mf = 0; mf < MFRAG; ++mf)
#pragma unroll
                for (int nt = 0; nt < 4; ++nt)
                    mma_f16(acc[mf][nt], a[mf], b[nt]);
        }
    }

    // epilogue: bias (+relu), fp32 and/or fp16 stores
#pragma unroll
    for (int mf = 0; mf < MFRAG; ++mf) {
        int rbase = row0 + wm * MFRAG * 16 + mf * 16 + g;
#pragma unroll
        for (int nt = 0; nt < 4; ++nt) {
            int cl = wn * 32 + nt * 8 + tig * 2;
            float2 bb = __ldg((const float2*)(bias + cl));
            float2 o0, o1;
            o0.x = acc[mf][nt][0] + bb.x;
            o0.y = acc[mf][nt][1] + bb.y;
            o1.x = acc[mf][nt][2] + bb.x;
            o1.y = acc[mf][nt][3] + bb.y;
            if (DO_RELU) {
                o0.x = fmaxf(o0.x, 0.f); o0.y = fmaxf(o0.y, 0.f);
                o1.x = fmaxf(o1.x, 0.f); o1.y = fmaxf(o1.y, 0.f);
            }
            if (rbase < n) {
                if (WRITE_F32)
                    *(float2*)(out + (size_t)rbase * 128 + cl) = o0;
                if (WRITE_HALF)
                    *(__half2*)(outh + (size_t)rbase * 128 + cl) =
                        __floats2half2_rn(o0.x, o0.y);
            }
            if (rbase + 8 < n) {
                if (WRITE_F32)
                    *(float2*)(out + (size_t)(rbase + 8) * 128 + cl) = o1;
                if (WRITE_HALF)
                    *(__half2*)(outh + (size_t)(rbase + 8) * 128 + cl) =
                        __floats2half2_rn(o1.x, o1.y);
            }
        }
    }
}

// ---------------- host launcher --------------------------------------------
extern "C" void kernel_launch(void* const* d_in, const int* in_sizes, int n_in,
                              void* d_out, int out_size) {
    int ix = 0, is1 = 1, id1 = 2, is2 = 3, id2 = 4;
    int iemb, ig, ib, iwl1, ibl1, iwr1, iwl2, ibl2, iwr2;
    if (n_in >= 16) {
        iemb = 7; ig = 8; ib = 9; iwl1 = 10; ibl1 = 11; iwr1 = 12;
        iwl2 = 13; ibl2 = 14; iwr2 = 15;
    } else {
        iemb = 5; ig = 6; ib = 7; iwl1 = 8; ibl1 = 9; iwr1 = 10;
        iwl2 = 11; ibl2 = 12; iwr2 = 13;
    }

    const int*   x    = (const int*)d_in[ix];
    const int*   src1 = (const int*)d_in[is1];
    const int*   dst1 = (const int*)d_in[id1];
    const int*   src2 = (const int*)d_in[is2];
    const int*   dst2 = (const int*)d_in[id2];
    const float* emb  = (const float*)d_in[iemb];
    const float* ln_g = (const float*)d_in[ig];
    const float* ln_b = (const float*)d_in[ib];
    const float* Wl1  = (const float*)d_in[iwl1];
    const float* bl1  = (const float*)d_in[ibl1];
    const float* Wr1  = (const float*)d_in[iwr1];
    const float* Wl2  = (const float*)d_in[iwl2];
    const float* bl2  = (const float*)d_in[ibl2];
    const float* Wr2  = (const float*)d_in[iwr2];

    int N0 = in_sizes[ix] / W_BAG;
    int E1 = in_sizes[is1]; if (E1 > E1_MAX) E1 = E1_MAX;
    int E2 = in_sizes[is2]; if (E2 > E2_MAX) E2 = E2_MAX;

    __half *h0h, *h1h, *A1, *A2, *wh1, *wh2;
    int *off1, *off2, *adj1, *adj2;
    cudaGetSymbolAddress((void**)&h0h,  g_h0h);
    cudaGetSymbolAddress((void**)&h1h,  g_h1h);
    cudaGetSymbolAddress((void**)&A1,   g_A1);
    cudaGetSymbolAddress((void**)&A2,   g_A2);
    cudaGetSymbolAddress((void**)&wh1,  g_Wh1);
    cudaGetSymbolAddress((void**)&wh2,  g_Wh2);
    cudaGetSymbolAddress((void**)&off1, g_off1);
    cudaGetSymbolAddress((void**)&off2, g_off2);
    cudaGetSymbolAddress((void**)&adj1, g_adj1);
    cudaGetSymbolAddress((void**)&adj2, g_adj2);

    // side stream + fork/join events
    cudaStream_t side;
    cudaStreamCreateWithFlags(&side, cudaStreamNonBlocking);
    cudaEvent_t eFork, eJoin;
    cudaEventCreateWithFlags(&eFork, cudaEventDisableTiming);
    cudaEventCreateWithFlags(&eJoin, cudaEventDisableTiming);

    // fork: CSR build overlaps init+embed
    cudaEventRecord(eFork, 0);
    cudaStreamWaitEvent(side, eFork, 0);

    int Etot = E1 + E2;
    zero_off<<<(N1_C + 1024) / 1024, 1024, 0, side>>>();
    hist_edges<<<(Etot + 255) / 256, 256, 0, side>>>(dst1, E1, dst2, E2);
    scan_blocks<<<NB1 + NB2, 1024, 0, side>>>();
    scan_add<<<NB1 + NB2, 1024, 0, side>>>();
    fill_edges<<<(Etot + 255) / 256, 256, 0, side>>>(src1, dst1, E1,
                                                     src2, dst2, E2);
    cudaEventRecord(eJoin, side);

    // main stream: init (fp16 weights + fp16 emb) then embed
    init_wemb<<<1024, 256>>>(Wl1, Wr1, Wl2, Wr2, emb);
    embed_ln_relu<<<(N0 * 32 + 255) / 256, 256>>>(x, ln_g, ln_b, N0);

    // join: pulls need both embed output and CSR
    cudaStreamWaitEvent(0, eJoin, 0);

    // layer-1 pull -> A1 (fp16), GEMM -> h1h (fp16)
    pull_mean<<<(N1_C * 32 + 255) / 256, 256>>>(h0h, off1, adj1, A1, N1_C);
    sage_gemm_f16<2, 1, 0, 1><<<(N1_C + 63) / 64, 256>>>(A1, wh1, bl1,
                                                         nullptr, h1h, N1_C);

    // layer-2 pull -> A2 (fp16), GEMM -> d_out (fp32)
    pull_mean<<<(N2_C * 32 + 255) / 256, 256>>>(h1h, off2, adj2, A2, N2_C);
    sage_gemm_f16<1, 0, 1, 0><<<(N2_C + 31) / 32, 256>>>(A2, wh2, bl2,
                                                         (float*)d_out, nullptr, N2_C);
}